// round 17
// baseline (speedup 1.0000x reference)
#include <cuda_runtime.h>

#define BATCH  64
#define NTOK   577
#define PTOK   576      // patches
#define DENS   288      // kept dense tokens
#define SSZ    288      // skipped tokens
#define GSZ    144      // selected group size
#define DIM    768
#define OUTROWS 433     // 1 + DENS + GSZ
#define RCOLS  432      // DENS + GSZ
#define EMAX   1200     // <= 4*288 = 1152 edges max
#define NPAIR  217      // ceil(OUTROWS/2) output row-pairs

// ---------------- scratch (device globals; no allocation) ----------------
__device__ int            g_order[BATCH][PTOK];     // argsort(-cls_attn)
__device__ int            g_t2[BATCH][SSZ][2];      // top-2 neighbor per skip row
__device__ int            g_rowmap[BATCH][OUTROWS]; // attention/tk row per output row
__device__ unsigned short g_colmap[BATCH][RCOLS];   // attention col per R column
__device__ int            g_ein[BATCH][EMAX];       // tk row of edge source (alive only)
__device__ float          g_ew[BATCH][EMAX];        // edge weight (alive only)
__device__ int            g_selrange[BATCH][GSZ][2];// compacted [start,end) per sel node
__device__ int            g_flag[BATCH];            // graph-done flag per batch

// ---------------- kernel A: argsort(-cls_attn) + flag reset ----------------
__global__ __launch_bounds__(192) void k_order(const float* __restrict__ attn) {
    const int b   = blockIdx.y;
    const int seg = blockIdx.x;                 // 0..3 -> elements seg*144..+143
    if (seg == 0 && threadIdx.x == 0) g_flag[b] = 0;   // reset per launch
    __shared__ float a[PTOK];
    for (int p = threadIdx.x; p < PTOK; p += 192)
        a[p] = attn[(size_t)b * NTOK * PTOK + p];
    __syncthreads();
    if (threadIdx.x < 144) {
        const int p = seg * 144 + threadIdx.x;
        const float v = a[p];
        int r = 0;
        const float4* a4 = (const float4*)a;
        #pragma unroll 4
        for (int q4 = 0; q4 < PTOK / 4; q4++) {
            float4 u4 = a4[q4];
            int qb = q4 * 4;
            r += (u4.x > v) || (u4.x == v && qb     < p);
            r += (u4.y > v) || (u4.y == v && qb + 1 < p);
            r += (u4.z > v) || (u4.z == v && qb + 2 < p);
            r += (u4.w > v) || (u4.w == v && qb + 3 < p);
        }
        g_order[b][r] = p;                      // ranks are unique -> disjoint
    }
}

// ---------------- kernel B: top-2 per skip row (1 warp per row) ------------
__global__ __launch_bounds__(256) void k_top2(const float* __restrict__ attn) {
    const int b    = blockIdx.y;
    const int warp = threadIdx.x >> 5;          // 8 warps
    const int lane = threadIdx.x & 31;
    const int i    = blockIdx.x * 8 + warp;     // skip row index 0..287

    __shared__ int   ords[SSZ];
    __shared__ float rows[8][PTOK];

    for (int j = threadIdx.x; j < SSZ; j += 256) ords[j] = g_order[b][DENS + j];
    __syncthreads();

    const int ri = 1 + ords[i];
    const float4* src4 = (const float4*)(attn + ((size_t)b * NTOK + ri) * PTOK);
    #pragma unroll
    for (int k = 0; k < PTOK / 4 / 32 + 1; k++) {
        int p = lane + k * 32;
        if (p < PTOK / 4) ((float4*)rows[warp])[p] = src4[p];
    }
    __syncwarp();

    unsigned long long k1 = 0ull, k2 = 0ull;
    #pragma unroll
    for (int k = 0; k < 9; k++) {
        int j = lane + k * 32;
        if (j == i) continue;
        float v = rows[warp][ords[j]];
        unsigned ub = __float_as_uint(v);
        ub ^= (unsigned)(((int)ub >> 31)) | 0x80000000u;   // total order on floats
        unsigned long long key = ((unsigned long long)ub << 32) | (unsigned)(SSZ - 1 - j);
        if (key > k1)      { k2 = k1; k1 = key; }
        else if (key > k2) { k2 = key; }
    }
    #pragma unroll
    for (int off = 16; off > 0; off >>= 1) {
        unsigned long long o1 = __shfl_down_sync(0xffffffffu, k1, off);
        unsigned long long o2 = __shfl_down_sync(0xffffffffu, k2, off);
        if (o1 > k1) { k2 = (k1 > o2) ? k1 : o2; k1 = o1; }
        else         { k2 = (k2 > o1) ? k2 : o1; }
    }
    if (lane == 0) {
        g_t2[b][i][0] = SSZ - 1 - (int)(k1 & 0xffffffffu);
        g_t2[b][i][1] = SSZ - 1 - (int)(k2 & 0xffffffffu);
    }
}

// ---------------- SMEM layouts for the fused kernel ------------------------
struct GraphSmem {
    int      order[PTOK];
    unsigned colbits[SSZ * 9];
    int      offs[SSZ + 1];
    int      coffs[SSZ + 1];
    int      ein[EMAX];
    float    ew[EMAX];
    unsigned char alive[EMAX];
    float    favg[2][SSZ];
    int      degi[SSZ];
    int      gsel[GSZ];
    int      wsum[9];
};
struct OutSmem {
    float          srow[2][PTOK];
    unsigned short cmap[RCOLS];
};

// ---- parallel exclusive scan over 288 per-thread values (288 threads) -----
__device__ __forceinline__ void scan288(int tid, int v, int* offs, int* wsum) {
    const int lane = tid & 31, warp = tid >> 5;     // 9 warps
    int incl = v;
    #pragma unroll
    for (int off = 1; off < 32; off <<= 1) {
        int n = __shfl_up_sync(0xffffffffu, incl, off);
        if (lane >= off) incl += n;
    }
    if (lane == 31) wsum[warp] = incl;
    __syncthreads();
    if (tid == 0) {
        int acc = 0;
        #pragma unroll
        for (int w = 0; w < 9; w++) { int t = wsum[w]; wsum[w] = acc; acc += t; }
        offs[SSZ] = acc;
    }
    __syncthreads();
    offs[tid] = incl - v + wsum[warp];
    __syncthreads();
}

// ---- per-row token computation --------------------------------------------
__device__ __forceinline__ void token_row(const float4* __restrict__ tk4,
                                          float* __restrict__ out,
                                          int b, int u, int row, int t) {
    float4 v = tk4[((size_t)b * NTOK + row) * (DIM / 4) + t];
    if (u > DENS) {                              // aggregated skip-selected row
        const int g  = u - 1 - DENS;
        const int st = g_selrange[b][g][0];
        const int en = g_selrange[b][g][1];
        float4 acc = make_float4(0.f, 0.f, 0.f, 0.f);
        for (int e = st; e < en; e++) {          // alive-only, ascending i
            float w  = g_ew[b][e];
            int   sr = g_ein[b][e];
            float4 sv = tk4[((size_t)b * NTOK + sr) * (DIM / 4) + t];
            acc.x += w * sv.x; acc.y += w * sv.y;
            acc.z += w * sv.z; acc.w += w * sv.w;
        }
        v.x = acc.x + v.x; v.y = acc.y + v.y;
        v.z = acc.z + v.z; v.w = acc.w + v.w;
    }
    __stcs(((float4*)out) + ((size_t)b * OUTROWS + u) * (DIM / 4) + t, v);
}

__device__ __forceinline__ void spin_on_flag(int b, int t) {
    if (t == 0) {
        while (atomicCAS(&g_flag[b], 1, 1) == 0) __nanosleep(128);
        __threadfence();
    }
    __syncthreads();
}

// --------- fused kernel: 64 graph blocks + 13888 output blocks -------------
__global__ __launch_bounds__(288) void k_gout(const float* __restrict__ tk,
                                              const float* __restrict__ attn,
                                              float* __restrict__ out) {
    __shared__ __align__(16) char smraw[sizeof(GraphSmem)];
    const int t = threadIdx.x;

    if (blockIdx.x < BATCH) {
        // ================= graph path (one block per batch) =================
        GraphSmem& S = *reinterpret_cast<GraphSmem*>(smraw);
        const int b   = blockIdx.x;
        const int tid = t;
        const float* A0 = attn + (size_t)b * NTOK * PTOK;

        for (int p = tid; p < PTOK; p += 288) S.order[p] = g_order[b][p];
        for (int k = tid; k < SSZ * 9; k += 288) S.colbits[k] = 0;
        __syncthreads();

        {   // symmetrize (column-major bit store)
            const int i = tid;
            const int j1 = g_t2[b][i][0], j2 = g_t2[b][i][1];
            atomicOr(&S.colbits[j1 * 9 + (i >> 5)], 1u << (i & 31));
            atomicOr(&S.colbits[j2 * 9 + (i >> 5)], 1u << (i & 31));
            atomicOr(&S.colbits[i * 9 + (j1 >> 5)], 1u << (j1 & 31));
            atomicOr(&S.colbits[i * 9 + (j2 >> 5)], 1u << (j2 & 31));
        }
        __syncthreads();

        int mycnt = 0;
        #pragma unroll
        for (int w = 0; w < 9; w++) mycnt += __popc(S.colbits[tid * 9 + w]);
        scan288(tid, mycnt, S.offs, S.wsum);

        const int j = tid, st0 = S.offs[j], en0 = S.offs[j + 1];

        {   // CSR fill (i ascending). M = (W != 0)
            const int cj = S.order[DENS + j];
            int ptr = st0;
            #pragma unroll
            for (int w = 0; w < 9; w++) {
                unsigned m = S.colbits[j * 9 + w];
                while (m) {
                    int i = w * 32 + __ffs(m) - 1;
                    m &= m - 1;
                    float wv = A0[(size_t)(1 + S.order[DENS + i]) * PTOK + cj];
                    S.ein[ptr] = i;
                    S.ew[ptr]  = wv;
                    S.alive[ptr] = (wv != 0.f) ? 1 : 0;
                    ptr++;
                }
            }
        }

        int cur = 0;
        {   // initial averages
            int dg = 0; float sm = 0.f;
            for (int e = st0; e < en0; e++)
                if (S.alive[e]) { dg++; sm += S.ew[e]; }
            S.degi[j] = dg;
            S.favg[0][j] = (dg > 0) ? (sm / (float)dg) : 0.f;
        }
        __syncthreads();

        for (;;) {  // fixed point, one barrier-op per iteration
            const float aj = S.favg[cur][j];
            int ch = 0;
            for (int e = st0; e < en0; e++)
                if (S.alive[e] && !(aj > S.favg[cur][S.ein[e]])) { S.alive[e] = 0; ch = 1; }
            int dg = 0; float sm = 0.f;
            for (int e = st0; e < en0; e++)
                if (S.alive[e]) { dg++; sm += S.ew[e]; }
            S.degi[j] = dg;
            S.favg[cur ^ 1][j] = (dg > 0) ? (sm / (float)dg) : 0.f;
            if (!__syncthreads_or(ch)) break;
            cur ^= 1;
        }

        scan288(tid, S.degi[tid], S.coffs, S.wsum);

        {   // top-144 by in-degree (ties -> smaller index first)
            const int dj = S.degi[j];
            int r = 0;
            for (int q = 0; q < SSZ; q++) {
                int dq = S.degi[q];
                r += (dq > dj) || (dq == dj && q < j);
            }
            if (r < GSZ) S.gsel[r] = j;
        }

        {   // compacted alive edges (tk-row-resolved), ascending i
            int ptr = S.coffs[j];
            for (int e = st0; e < en0; e++) {
                if (S.alive[e]) {
                    g_ein[b][ptr] = 1 + S.order[DENS + S.ein[e]];
                    g_ew[b][ptr]  = S.ew[e];
                    ptr++;
                }
            }
        }
        __syncthreads();

        for (int g = tid; g < GSZ; g += 288) {
            int jj = S.gsel[g];
            g_selrange[b][g][0] = S.coffs[jj];
            g_selrange[b][g][1] = S.coffs[jj] + S.degi[jj];
        }
        for (int u = tid; u < OUTROWS; u += 288) {
            int row;
            if (u == 0)            row = 0;
            else if (u <= DENS)    row = 1 + S.order[u - 1];
            else                   row = 1 + S.order[DENS + S.gsel[u - 1 - DENS]];
            g_rowmap[b][u] = row;
        }
        for (int v = tid; v < RCOLS; v += 288) {
            int c;
            if (v < DENS) c = S.order[v];
            else          c = S.order[DENS + S.gsel[v - DENS]];
            g_colmap[b][v] = (unsigned short)c;
        }
        __syncthreads();
        __threadfence();
        if (tid == 0) atomicExch(&g_flag[b], 1);   // release
        return;
    }

    // ================= output path (2 adjacent rows per block) ==============
    OutSmem& O = *reinterpret_cast<OutSmem*>(smraw);
    const int s  = blockIdx.x - BATCH;            // 0..13887
    const int ps = s >> 6;                        // schedule slot 0..216
    const int b  = s & 63;
    // schedule: 75 dense pairs (cover graph latency), 72 agg pairs, 70 dense
    const int pj = (ps < 75) ? (72 + ps) : ((ps < 147) ? (ps - 75) : ps);
    const int uA = OUTROWS - 1 - 2 * pj;          // even
    const int uB = uA - 1;                        // odd or -1
    const bool needB = (uB >= 0);
    float* outR = out + (size_t)BATCH * OUTROWS * DIM;
    const float4* tk4 = (const float4*)tk;

    if (uA > DENS) {
        // ---- aggregated pair: needs the graph; scheduled late -> flag set ----
        spin_on_flag(b, t);
        const int rowA = g_rowmap[b][uA];
        const int rowB = g_rowmap[b][uB];
        const float4* aA = (const float4*)(attn + ((size_t)b * NTOK + rowA) * PTOK);
        const float4* aB = (const float4*)(attn + ((size_t)b * NTOK + rowB) * PTOK);
        if (t < 144)       ((float4*)O.srow[0])[t]       = aA[t];
        else if (t < 288)  ((float4*)O.srow[1])[t - 144] = aB[t - 144];
        if (t < RCOLS)            O.cmap[t]       = g_colmap[b][t];
        if (t + 288 < RCOLS)      O.cmap[t + 288] = g_colmap[b][t + 288];
        if (t < 192) {
            token_row(tk4, out, b, uA, rowA, t);
            token_row(tk4, out, b, uB, rowB, t);
        }
        __syncthreads();
        if (t < RCOLS / 4) {
            const int i0 = t * 4;
            const int c0 = O.cmap[i0], c1 = O.cmap[i0+1], c2 = O.cmap[i0+2], c3 = O.cmap[i0+3];
            float4 r;
            r.x = O.srow[0][c0]; r.y = O.srow[0][c1]; r.z = O.srow[0][c2]; r.w = O.srow[0][c3];
            __stcs((float4*)(outR + ((size_t)b * OUTROWS + uA) * RCOLS) + t, r);
            r.x = O.srow[1][c0]; r.y = O.srow[1][c1]; r.z = O.srow[1][c2]; r.w = O.srow[1][c3];
            __stcs((float4*)(outR + ((size_t)b * OUTROWS + uB) * RCOLS) + t, r);
        }
    } else {
        // ---- dense pair: order-only work first, graph needed only for R-hi ---
        const int rowA = (uA == 0) ? 0 : 1 + g_order[b][uA - 1];
        const int rowB = needB ? (1 + g_order[b][uB - 1]) : rowA;
        const float4* aA = (const float4*)(attn + ((size_t)b * NTOK + rowA) * PTOK);
        const float4* aB = (const float4*)(attn + ((size_t)b * NTOK + rowB) * PTOK);
        if (t < 144)       ((float4*)O.srow[0])[t]       = aA[t];
        else if (t < 288)  ((float4*)O.srow[1])[t - 144] = aB[t - 144];
        O.cmap[t] = (unsigned short)g_order[b][t];       // cols 0..287
        if (t < 192) {
            token_row(tk4, out, b, uA, rowA, t);
            if (needB) token_row(tk4, out, b, uB, rowB, t);
        }
        __syncthreads();                                  // srow + cmap-lo ready
        if (t < DENS / 4) {                               // R cols 0..287
            const int i0 = t * 4;
            const int c0 = O.cmap[i0], c1 = O.cmap[i0+1], c2 = O.cmap[i0+2], c3 = O.cmap[i0+3];
            float4 r;
            r.x = O.srow[0][c0]; r.y = O.srow[0][c1]; r.z = O.srow[0][c2]; r.w = O.srow[0][c3];
            __stcs((float4*)(outR + ((size_t)b * OUTROWS + uA) * RCOLS) + t, r);
            if (needB) {
                r.x = O.srow[1][c0]; r.y = O.srow[1][c1]; r.z = O.srow[1][c2]; r.w = O.srow[1][c3];
                __stcs((float4*)(outR + ((size_t)b * OUTROWS + uB) * RCOLS) + t, r);
            }
        }
        spin_on_flag(b, t);                               // graph done?
        if (t < GSZ) O.cmap[DENS + t] = g_colmap[b][DENS + t];
        __syncthreads();
        if (t >= DENS / 4 && t < RCOLS / 4) {             // R cols 288..431
            const int i0 = t * 4;
            const int c0 = O.cmap[i0], c1 = O.cmap[i0+1], c2 = O.cmap[i0+2], c3 = O.cmap[i0+3];
            float4 r;
            r.x = O.srow[0][c0]; r.y = O.srow[0][c1]; r.z = O.srow[0][c2]; r.w = O.srow[0][c3];
            __stcs((float4*)(outR + ((size_t)b * OUTROWS + uA) * RCOLS) + t, r);
            if (needB) {
                r.x = O.srow[1][c0]; r.y = O.srow[1][c1]; r.z = O.srow[1][c2]; r.w = O.srow[1][c3];
                __stcs((float4*)(outR + ((size_t)b * OUTROWS + uB) * RCOLS) + t, r);
            }
        }
    }
}

// ---------------- launch ---------------------------------------------------
extern "C" void kernel_launch(void* const* d_in, const int* in_sizes, int n_in,
                              void* d_out, int out_size) {
    const float* tk   = (const float*)d_in[0];
    const float* attn = (const float*)d_in[1];
    float* out = (float*)d_out;

    k_order <<<dim3(4, BATCH), 192>>>(attn);
    k_top2  <<<dim3(SSZ / 8, BATCH), 256>>>(attn);
    k_gout  <<<BATCH + NPAIR * BATCH, 288>>>(tk, attn, out);
}